// round 13
// baseline (speedup 1.0000x reference)
#include <cuda_runtime.h>
#include <cuda_fp16.h>
#include <math_constants.h>
#include <cstdint>

// ---------------- problem constants ----------------
#define B_   16
#define S_   2048
#define D_   512
#define C_   8192
#define NTOK (B_*S_)

// ---------------- tiling ----------------
#define BM 128
#define BN 256                    // codes per chunk
#define KS 64                     // K per slab
#define NKS (D_/KS)               // 8
#define QCODES (C_/4)             // 2048 codes per quarter job
#define QCH (QCODES/BN)           // 8 chunks per job
#define NSLJ (QCH*NKS)            // 64 slabs per job
#define TILE_A 16384              // 128 rows x 128B fp16
#define TILE_B 32768              // 256 rows x 128B fp16
#define ST_B (TILE_A+TILE_B)      // 48KB per stage
#define NSTAGE 2
#define DYN_SMEM (NSTAGE*ST_B)    // 96KB
#define NTHREADS 256
#define NTILES (NTOK/BM)          // 256 token tiles
#define GRID 296                  // 2 CTAs per SM

// ---------------- device scratch ----------------
__device__ __half g_xh[NTOK*D_];
__device__ __half g_eh[C_*D_];
__device__ float  g_e2h[C_];
__device__ float2 g_part[NTOK*4];   // per (token, quarter): {val, idx-bits}
__device__ int    g_active[NTILES];
__device__ int    g_nactive;
__device__ int    g_counter;

// ---------------- helpers ----------------
__device__ __forceinline__ uint32_t smem_u32(const void* p) {
    uint32_t a;
    asm("{ .reg .u64 t; cvta.to.shared.u64 t, %1; cvt.u32.u64 %0, t; }" : "=r"(a) : "l"(p));
    return a;
}
__device__ __forceinline__ void cp_async16(uint32_t saddr, const void* gptr) {
    asm volatile("cp.async.cg.shared.global [%0], [%1], 16;\n" :: "r"(saddr), "l"(gptr));
}
__device__ __forceinline__ void cp_commit() { asm volatile("cp.async.commit_group;\n"); }
__device__ __forceinline__ void cp_wait1()  { asm volatile("cp.async.wait_group 1;\n" ::: "memory"); }
__device__ __forceinline__ void cp_wait0()  { asm volatile("cp.async.wait_group 0;\n" ::: "memory"); }

__device__ __forceinline__ void ldsm4(uint32_t* r, uint32_t addr) {
    asm volatile("ldmatrix.sync.aligned.m8n8.x4.shared.b16 {%0,%1,%2,%3}, [%4];"
                 : "=r"(r[0]), "=r"(r[1]), "=r"(r[2]), "=r"(r[3]) : "r"(addr));
}
// fp16-accumulator MMA: d/c are 2 b32 regs (4 halves)
__device__ __forceinline__ void mma_f16acc(uint32_t* d, const uint32_t* a, const uint32_t* b) {
    asm("mma.sync.aligned.m16n8k16.row.col.f16.f16.f16.f16 "
        "{%0,%1}, {%2,%3,%4,%5}, {%6,%7}, {%0,%1};"
        : "+r"(d[0]), "+r"(d[1])
        : "r"(a[0]), "r"(a[1]), "r"(a[2]), "r"(a[3]), "r"(b[0]), "r"(b[1]));
}

__device__ __forceinline__ bool better(float a, int ia, float b, int ib) {
    return (a > b) || (a == b && ia < ib);
}
__device__ __forceinline__ void upd2(float& v1, int& i1, float& v2, int& i2, float s, int c) {
    if (better(s, c, v1, i1)) { v2 = v1; i2 = i1; v1 = s; i1 = c; }
    else if (better(s, c, v2, i2)) { v2 = s; i2 = c; }
}
__device__ __forceinline__ void merge2(float& v1, int& i1, float& v2, int& i2,
                                       float w1, int j1, float w2, int j2) {
    if (better(w1, j1, v1, i1)) {
        if (better(v1, i1, w2, j2)) { v2 = v1; i2 = i1; } else { v2 = w2; i2 = j2; }
        v1 = w1; i1 = j1;
    } else if (better(w1, j1, v2, i2)) { v2 = w1; i2 = j1; }
}

// ---------------- prep kernels ----------------
__global__ void conv_x_kernel(const float* __restrict__ src, int n8) {
    int i = blockIdx.x * blockDim.x + threadIdx.x;
    if (i >= n8) return;
    const float4* s4 = reinterpret_cast<const float4*>(src);
    float4 v0 = s4[2 * i], v1 = s4[2 * i + 1];
    float vv[8] = {v0.x, v0.y, v0.z, v0.w, v1.x, v1.y, v1.z, v1.w};
    __align__(16) __half h[8];
    #pragma unroll
    for (int k = 0; k < 8; k++) h[k] = __float2half(vv[k]);
    reinterpret_cast<uint4*>(g_xh)[i] = *reinterpret_cast<uint4*>(h);
}

__global__ void conv_e_kernel(const float* __restrict__ embed) {
    int warp = threadIdx.x >> 5, lane = threadIdx.x & 31;
    int c = blockIdx.x * 8 + warp;
    if (c >= C_) return;
    const float* row = embed + (size_t)c * D_;
    float s = 0.f;
    #pragma unroll
    for (int i = lane; i < D_ / 8; i += 32) {
        const float4* s4 = reinterpret_cast<const float4*>(row) + 2 * i;
        float4 v0 = s4[0], v1 = s4[1];
        float vv[8] = {v0.x, v0.y, v0.z, v0.w, v1.x, v1.y, v1.z, v1.w};
        __align__(16) __half h[8];
        #pragma unroll
        for (int k = 0; k < 8; k++) {
            h[k] = __float2half(vv[k]);
            s = fmaf(vv[k], vv[k], s);
        }
        reinterpret_cast<uint4*>(g_eh + (size_t)c * D_)[i] = *reinterpret_cast<uint4*>(h);
    }
    #pragma unroll
    for (int o = 16; o > 0; o >>= 1) s += __shfl_xor_sync(0xffffffffu, s, o);
    if (lane == 0) g_e2h[c] = 0.5f * s;
}

__global__ void build_kernel(const int* __restrict__ input_length) {
    __shared__ int cnt;
    int t = threadIdx.x;
    if (t == 0) { cnt = 0; g_counter = 0; }
    __syncthreads();
    if (t < NTILES) {
        int batch = t >> 4, tile = t & 15;
        if (input_length[batch] > tile * BM) {
            int p = atomicAdd(&cnt, 1); g_active[p] = t;
        }
    }
    __syncthreads();
    if (t == 0) g_nactive = cnt;
}

// ---------------- main MMA kernel (2 CTAs/SM) ----------------
__global__ void __launch_bounds__(NTHREADS, 2)
vq_mma_kernel(const float* __restrict__ x,
              const int*   __restrict__ input_length,
              const float* __restrict__ embed,
              float*       __restrict__ out)
{
    extern __shared__ char dsm[];
    __shared__ float4 red[4][BM];   // per warp_n group, per row: top-2
    __shared__ float  se2[BN];
    __shared__ int    s_job;

    const int tid    = threadIdx.x;
    const int wid    = tid >> 5;
    const int lane   = tid & 31;
    const int warp_m = wid & 1;     // 0..1 : 64 rows each
    const int warp_n = wid >> 1;    // 0..3 : 64 cols each
    const int g      = lane >> 2;
    const int tig    = lane & 3;

    const uint32_t dbase = smem_u32(dsm);

    // loader geometry
    uint32_t ldA_off[4]; int ldA_rowD[4];
    #pragma unroll
    for (int rep = 0; rep < 4; rep++) {
        int idx = tid + rep * NTHREADS;      // 0..1023 -> 16KB
        int row = idx >> 3, ch = idx & 7;
        ldA_off[rep]  = (uint32_t)(row * 128) + (uint32_t)((ch ^ (row & 7)) << 4);
        ldA_rowD[rep] = row * D_ + ch * 8;
    }
    uint32_t ldB_off[8]; int ldB_rowD[8];
    #pragma unroll
    for (int rep = 0; rep < 8; rep++) {
        int idx = tid + rep * NTHREADS;      // 0..2047 -> 32KB
        int row = idx >> 3, ch = idx & 7;
        ldB_off[rep]  = (uint32_t)(row * 128) + (uint32_t)((ch ^ (row & 7)) << 4);
        ldB_rowD[rep] = row * D_ + ch * 8;
    }

    // per-lane ldmatrix geometry
    const int arow_l   = (lane & 7) + (((lane >> 3) & 1) << 3);
    const int achunk_l = (lane >> 4);
    const int brow_l   = (lane & 7) + (((lane >> 4) & 1) << 3);
    const int bchunk_l = (lane >> 3) & 1;
    const int rmod     = lane & 7;

    uint32_t abase[4];
    #pragma unroll
    for (int mt = 0; mt < 4; mt++)
        abase[mt] = (uint32_t)((warp_m * 64 + mt * 16 + arow_l) * 128);
    uint32_t bbase[4];
    #pragma unroll
    for (int np = 0; np < 4; np++)
        bbase[np] = (uint32_t)((warp_n * 64 + np * 16 + brow_l) * 128);

    while (true) {
        __syncthreads();
        if (tid == 0) s_job = atomicAdd(&g_counter, 1);
        __syncthreads();
        int job = s_job;
        if (job >= 4 * g_nactive) break;
        const int bt = g_active[job >> 2];
        const int q  = job & 3;
        const int token0 = bt * BM;
        const int qbase  = q * QCODES;

        const size_t abase_g = (size_t)token0 * D_;
        const size_t qbase_g = (size_t)qbase * D_;

        // per-row top-2 for each of 4 warp_n groups (threads 0..127)
        float rv[4][2]; int ri[4][2];
        #pragma unroll
        for (int gg = 0; gg < 4; gg++) {
            rv[gg][0] = -CUDART_INF_F; rv[gg][1] = -CUDART_INF_F;
            ri[gg][0] = 0; ri[gg][1] = 0;
        }

        auto issue = [&](int s) {
            uint32_t sb = dbase + (uint32_t)(s & 1) * ST_B;
            const size_t koff = (size_t)((s & 7) * KS);
            const size_t bg = qbase_g + (size_t)((s >> 3) * BN) * D_ + koff;
            #pragma unroll
            for (int rep = 0; rep < 4; rep++)
                cp_async16(sb + ldA_off[rep], g_xh + abase_g + ldA_rowD[rep] + koff);
            #pragma unroll
            for (int rep = 0; rep < 8; rep++)
                cp_async16(sb + TILE_A + ldB_off[rep], g_eh + bg + ldB_rowD[rep]);
            cp_commit();
        };

        issue(0);
        issue(1);

        uint32_t acc[4][8][2];   // fp16x2 accumulators

        #pragma unroll 1
        for (int s = 0; s < NSLJ; s++) {
            const int c = s >> 3, ks = s & 7;
            if (s + 1 < NSLJ) cp_wait1(); else cp_wait0();
            __syncthreads();

            if (ks == 0) {
                se2[tid] = g_e2h[qbase + c * BN + tid];   // BN == NTHREADS
                #pragma unroll
                for (int mt = 0; mt < 4; mt++)
                    #pragma unroll
                    for (int nt = 0; nt < 8; nt++) {
                        acc[mt][nt][0] = 0u; acc[mt][nt][1] = 0u;
                    }
            }

            const uint32_t sb = dbase + (uint32_t)(s & 1) * ST_B;
            const uint32_t aH = sb;
            const uint32_t bH = sb + TILE_A;

            #pragma unroll
            for (int kk = 0; kk < 4; kk++) {
                uint32_t ah[4][4];
                #pragma unroll
                for (int mt = 0; mt < 4; mt++) {
                    uint32_t off = abase[mt] + (uint32_t)((((kk * 2) + achunk_l) ^ rmod) << 4);
                    ldsm4(ah[mt], aH + off);
                }
                #pragma unroll
                for (int np = 0; np < 4; np++) {
                    uint32_t off = bbase[np] + (uint32_t)((((kk * 2) + bchunk_l) ^ rmod) << 4);
                    uint32_t bh[4];
                    ldsm4(bh, bH + off);
                    #pragma unroll
                    for (int half = 0; half < 2; half++) {
                        const int nt = 2 * np + half;
                        #pragma unroll
                        for (int mt = 0; mt < 4; mt++)
                            mma_f16acc(acc[mt][nt], ah[mt], bh + 2 * half);
                    }
                }
            }

            __syncthreads();                 // all reads of stage (s&1) done
            if (s + 2 < NSLJ) issue(s + 2);  // refill it

            if (ks == 7) {
                // per-chunk argmax epilogue (per warp: 64 rows x 64 cols)
                #pragma unroll
                for (int mt = 0; mt < 4; mt++) {
                    float v1a = -CUDART_INF_F, v2a = -CUDART_INF_F;
                    float v1b = -CUDART_INF_F, v2b = -CUDART_INF_F;
                    int   i1a = 0, i2a = 0, i1b = 0, i2b = 0;
                    #pragma unroll
                    for (int nt = 0; nt < 8; nt++) {
                        int colb = warp_n * 64 + nt * 8 + tig * 2;
                        float e0 = se2[colb], e1 = se2[colb + 1];
                        int code0 = qbase + c * BN + colb;
                        __half2 h0 = *reinterpret_cast<const __half2*>(&acc[mt][nt][0]);
                        __half2 h1 = *reinterpret_cast<const __half2*>(&acc[mt][nt][1]);
                        float2 f0 = __half22float2(h0);
                        float2 f1 = __half22float2(h1);
                        upd2(v1a, i1a, v2a, i2a, f0.x - e0, code0);
                        upd2(v1a, i1a, v2a, i2a, f0.y - e1, code0 + 1);
                        upd2(v1b, i1b, v2b, i2b, f1.x - e0, code0);
                        upd2(v1b, i1b, v2b, i2b, f1.y - e1, code0 + 1);
                    }
                    #pragma unroll
                    for (int off = 1; off < 4; off <<= 1) {
                        float w1 = __shfl_xor_sync(0xffffffffu, v1a, off);
                        int   j1 = __shfl_xor_sync(0xffffffffu, i1a, off);
                        float w2 = __shfl_xor_sync(0xffffffffu, v2a, off);
                        int   j2 = __shfl_xor_sync(0xffffffffu, i2a, off);
                        merge2(v1a, i1a, v2a, i2a, w1, j1, w2, j2);
                        w1 = __shfl_xor_sync(0xffffffffu, v1b, off);
                        j1 = __shfl_xor_sync(0xffffffffu, i1b, off);
                        w2 = __shfl_xor_sync(0xffffffffu, v2b, off);
                        j2 = __shfl_xor_sync(0xffffffffu, i2b, off);
                        merge2(v1b, i1b, v2b, i2b, w1, j1, w2, j2);
                    }
                    if (tig == 0) {
                        int r0 = warp_m * 64 + mt * 16 + g;
                        red[warp_n][r0]     = make_float4(v1a, __int_as_float(i1a),
                                                          v2a, __int_as_float(i2a));
                        red[warp_n][r0 + 8] = make_float4(v1b, __int_as_float(i1b),
                                                          v2b, __int_as_float(i2b));
                    }
                }
                __syncthreads();
                if (tid < BM) {
                    #pragma unroll
                    for (int wn = 0; wn < 4; wn++) {
                        float4 r0 = red[wn][tid];
                        merge2(rv[wn][0], ri[wn][0], rv[wn][1], ri[wn][1],
                               r0.x, __float_as_int(r0.y), r0.z, __float_as_int(r0.w));
                    }
                }
                // next slab's leading __syncthreads orders red reuse
            }
        }

        // ---- exact fp32 rescore of 8 candidates; write per-quarter result ----
        __syncthreads();
        if (tid < BM) {
            int row = tid;
            int token = token0 + row;
            const float* xr = x + (size_t)token * D_;
            float bv = -CUDART_INF_F; int bi = 0x7fffffff;
            #pragma unroll
            for (int gg = 0; gg < 4; gg++) {
                #pragma unroll
                for (int k = 0; k < 2; k++) {
                    int cidx = ri[gg][k];
                    const float* ep = embed + (size_t)cidx * D_;
                    float sdot = 0.f;
                    #pragma unroll 4
                    for (int d = 0; d < D_; d += 4) {
                        float4 xv = *reinterpret_cast<const float4*>(xr + d);
                        float4 ev = *reinterpret_cast<const float4*>(ep + d);
                        sdot = fmaf(xv.x, ev.x, sdot); sdot = fmaf(xv.y, ev.y, sdot);
                        sdot = fmaf(xv.z, ev.z, sdot); sdot = fmaf(xv.w, ev.w, sdot);
                    }
                    sdot -= __ldg(&g_e2h[cidx]);
                    if (better(sdot, cidx, bv, bi)) { bv = sdot; bi = cidx; }
                }
            }
            g_part[(token << 2) | q] = make_float2(bv, __int_as_float(bi));
        }
    }
}

// ---------------- combine: cross-quarter argmax + gather + mask ----------------
__global__ void combine_kernel(const int* __restrict__ input_length,
                               const float* __restrict__ embed,
                               float* __restrict__ out)
{
    __shared__ int sIdx[128];
    const int bt = blockIdx.x;
    const int token0 = bt * 128;
    const int batch = token0 >> 11;
    const int len = input_length[batch];
    int active = len - (token0 & 2047);
    active = active < 0 ? 0 : (active > 128 ? 128 : active);
    const int tid = threadIdx.x;

    float* outi = out + (size_t)NTOK * D_;

    if (tid < 128) {
        int token = token0 + tid;
        float bv = -CUDART_INF_F; int bi = 0x7fffffff;
        if (tid < active) {
            #pragma unroll
            for (int q = 0; q < 4; q++) {
                float2 p = g_part[(token << 2) | q];
                int ii = __float_as_int(p.y);
                if (better(p.x, ii, bv, bi)) { bv = p.x; bi = ii; }
            }
        }
        sIdx[tid] = bi;
        outi[token] = (tid < active) ? (float)bi : -1.0f;
    }
    __syncthreads();

    float4* qo = reinterpret_cast<float4*>(out + (size_t)token0 * D_);
    const float4 z = make_float4(0.f, 0.f, 0.f, 0.f);
    for (int v = tid; v < 128 * (D_ / 4); v += 256) {
        int r  = v >> 7;
        int dc = v & 127;
        float4 val = z;
        if (r < active)
            val = reinterpret_cast<const float4*>(embed + (size_t)sIdx[r] * D_)[dc];
        qo[v] = val;
    }
}

// ---------------------------------------------------------------------------
extern "C" void kernel_launch(void* const* d_in, const int* in_sizes, int n_in,
                              void* d_out, int out_size)
{
    const float* x     = (const float*)d_in[0];
    const int*   ilen  = (const int*)  d_in[1];
    const float* embed = (const float*)d_in[2];
    float* out = (float*)d_out;

    cudaFuncSetAttribute(vq_mma_kernel,
                         cudaFuncAttributeMaxDynamicSharedMemorySize, DYN_SMEM);

    conv_x_kernel<<<(NTOK * D_ / 8 + 255) / 256, 256>>>(x, NTOK * D_ / 8);
    conv_e_kernel<<<C_ / 8, 256>>>(embed);
    build_kernel<<<1, 256>>>(ilen);
    vq_mma_kernel<<<GRID, NTHREADS, DYN_SMEM>>>(x, ilen, embed, out);
    combine_kernel<<<NTOK / 128, 256>>>(ilen, embed, out);
}

// round 14
// speedup vs baseline: 1.2150x; 1.2150x over previous
#include <cuda_runtime.h>
#include <cuda_fp16.h>
#include <math_constants.h>
#include <cstdint>

// ---------------- problem constants ----------------
#define B_   16
#define S_   2048
#define D_   512
#define C_   8192
#define NTOK (B_*S_)

// ---------------- tiling (R12 geometry, fp16 accumulators) ----------------
#define BM 128
#define BN 128
#define KS 64                     // K per slab
#define NKS (D_/KS)               // 8
#define QCODES (C_/4)             // 2048 codes per quarter job
#define QCH (QCODES/BN)           // 16 chunks per job
#define NSLJ (QCH*NKS)            // 128 slabs per job
#define TILE16 16384              // 128 rows x 128B fp16 tile
#define ST_B (2*TILE16)           // A, B = 32KB per stage
#define NSTAGE 3
#define DYN_SMEM (NSTAGE*ST_B)    // 96KB
#define NTHREADS 256
#define NTILES (NTOK/BM)          // 256 token tiles
#define GRID 296                  // 2 CTAs per SM

// ---------------- device scratch ----------------
__device__ __half g_xh[NTOK*D_];
__device__ __half g_eh[C_*D_];
__device__ float  g_e2h[C_];
__device__ float2 g_part[NTOK*4];   // per (token, quarter): {val, idx-bits}
__device__ int    g_active[NTILES];
__device__ int    g_nactive;
__device__ int    g_counter;

// ---------------- helpers ----------------
__device__ __forceinline__ uint32_t smem_u32(const void* p) {
    uint32_t a;
    asm("{ .reg .u64 t; cvta.to.shared.u64 t, %1; cvt.u32.u64 %0, t; }" : "=r"(a) : "l"(p));
    return a;
}
__device__ __forceinline__ void cp_async16(uint32_t saddr, const void* gptr) {
    asm volatile("cp.async.cg.shared.global [%0], [%1], 16;\n" :: "r"(saddr), "l"(gptr));
}
__device__ __forceinline__ void cp_commit() { asm volatile("cp.async.commit_group;\n"); }
__device__ __forceinline__ void cp_wait1()  { asm volatile("cp.async.wait_group 1;\n" ::: "memory"); }
__device__ __forceinline__ void cp_wait0()  { asm volatile("cp.async.wait_group 0;\n" ::: "memory"); }

__device__ __forceinline__ void ldsm4(uint32_t* r, uint32_t addr) {
    asm volatile("ldmatrix.sync.aligned.m8n8.x4.shared.b16 {%0,%1,%2,%3}, [%4];"
                 : "=r"(r[0]), "=r"(r[1]), "=r"(r[2]), "=r"(r[3]) : "r"(addr));
}
// fp16-accumulator MMA: d is 2 b32 regs (reg0 = row g, reg1 = row g+8)
__device__ __forceinline__ void mma_f16acc(uint32_t* d, const uint32_t* a, const uint32_t* b) {
    asm("mma.sync.aligned.m16n8k16.row.col.f16.f16.f16.f16 "
        "{%0,%1}, {%2,%3,%4,%5}, {%6,%7}, {%0,%1};"
        : "+r"(d[0]), "+r"(d[1])
        : "r"(a[0]), "r"(a[1]), "r"(a[2]), "r"(a[3]), "r"(b[0]), "r"(b[1]));
}

__device__ __forceinline__ bool better(float a, int ia, float b, int ib) {
    return (a > b) || (a == b && ia < ib);
}
__device__ __forceinline__ void upd2(float& v1, int& i1, float& v2, int& i2, float s, int c) {
    if (better(s, c, v1, i1)) { v2 = v1; i2 = i1; v1 = s; i1 = c; }
    else if (better(s, c, v2, i2)) { v2 = s; i2 = c; }
}
__device__ __forceinline__ void merge2(float& v1, int& i1, float& v2, int& i2,
                                       float w1, int j1, float w2, int j2) {
    if (better(w1, j1, v1, i1)) {
        if (better(v1, i1, w2, j2)) { v2 = v1; i2 = i1; } else { v2 = w2; i2 = j2; }
        v1 = w1; i1 = j1;
    } else if (better(w1, j1, v2, i2)) { v2 = w1; i2 = j1; }
}

// ---------------- prep kernels ----------------
__global__ void conv_x_kernel(const float* __restrict__ src, int n8) {
    int i = blockIdx.x * blockDim.x + threadIdx.x;
    if (i >= n8) return;
    const float4* s4 = reinterpret_cast<const float4*>(src);
    float4 v0 = s4[2 * i], v1 = s4[2 * i + 1];
    float vv[8] = {v0.x, v0.y, v0.z, v0.w, v1.x, v1.y, v1.z, v1.w};
    __align__(16) __half h[8];
    #pragma unroll
    for (int k = 0; k < 8; k++) h[k] = __float2half(vv[k]);
    reinterpret_cast<uint4*>(g_xh)[i] = *reinterpret_cast<uint4*>(h);
}

__global__ void conv_e_kernel(const float* __restrict__ embed) {
    int warp = threadIdx.x >> 5, lane = threadIdx.x & 31;
    int c = blockIdx.x * 8 + warp;
    if (c >= C_) return;
    const float* row = embed + (size_t)c * D_;
    float s = 0.f;
    #pragma unroll
    for (int i = lane; i < D_ / 8; i += 32) {
        const float4* s4 = reinterpret_cast<const float4*>(row) + 2 * i;
        float4 v0 = s4[0], v1 = s4[1];
        float vv[8] = {v0.x, v0.y, v0.z, v0.w, v1.x, v1.y, v1.z, v1.w};
        __align__(16) __half h[8];
        #pragma unroll
        for (int k = 0; k < 8; k++) {
            h[k] = __float2half(vv[k]);
            s = fmaf(vv[k], vv[k], s);
        }
        reinterpret_cast<uint4*>(g_eh + (size_t)c * D_)[i] = *reinterpret_cast<uint4*>(h);
    }
    #pragma unroll
    for (int o = 16; o > 0; o >>= 1) s += __shfl_xor_sync(0xffffffffu, s, o);
    if (lane == 0) g_e2h[c] = 0.5f * s;
}

__global__ void build_kernel(const int* __restrict__ input_length) {
    __shared__ int cnt;
    int t = threadIdx.x;
    if (t == 0) { cnt = 0; g_counter = 0; }
    __syncthreads();
    if (t < NTILES) {
        int batch = t >> 4, tile = t & 15;
        if (input_length[batch] > tile * BM) {
            int p = atomicAdd(&cnt, 1); g_active[p] = t;
        }
    }
    __syncthreads();
    if (t == 0) g_nactive = cnt;
}

// ---------------- main MMA kernel (2 CTAs/SM) ----------------
__global__ void __launch_bounds__(NTHREADS, 2)
vq_mma_kernel(const float* __restrict__ x,
              const int*   __restrict__ input_length,
              const float* __restrict__ embed,
              float*       __restrict__ out)
{
    extern __shared__ char dsm[];
    __shared__ float4 red[2][BM];
    __shared__ float  se2[BN];
    __shared__ int    s_job;

    const int tid    = threadIdx.x;
    const int wid    = tid >> 5;
    const int lane   = tid & 31;
    const int warp_m = wid & 3;     // 0..3 : 32 rows each
    const int warp_n = wid >> 2;    // 0..1 : 64 cols each
    const int g      = lane >> 2;
    const int tig    = lane & 3;

    const uint32_t dbase = smem_u32(dsm);

    // loader geometry: 4 reps x 2 tiles
    uint32_t ld_off[4]; int ld_rowD[4];
    #pragma unroll
    for (int rep = 0; rep < 4; rep++) {
        int idx = tid + rep * NTHREADS;
        int row = idx >> 3, ch = idx & 7;
        ld_off[rep]  = (uint32_t)(row * 128) + (uint32_t)((ch ^ (row & 7)) << 4);
        ld_rowD[rep] = row * D_ + ch * 8;
    }

    // per-lane ldmatrix geometry
    const int arow_l   = (lane & 7) + (((lane >> 3) & 1) << 3);
    const int achunk_l = (lane >> 4);
    const int brow_l   = (lane & 7) + (((lane >> 4) & 1) << 3);
    const int bchunk_l = (lane >> 3) & 1;
    const int rmod     = lane & 7;

    uint32_t abase[2];
    #pragma unroll
    for (int mt = 0; mt < 2; mt++)
        abase[mt] = (uint32_t)((warp_m * 32 + mt * 16 + arow_l) * 128);
    uint32_t bbase[4];
    #pragma unroll
    for (int np = 0; np < 4; np++)
        bbase[np] = (uint32_t)((warp_n * 64 + np * 16 + brow_l) * 128);

    while (true) {
        __syncthreads();
        if (tid == 0) s_job = atomicAdd(&g_counter, 1);
        __syncthreads();
        int job = s_job;
        if (job >= 4 * g_nactive) break;
        const int bt = g_active[job >> 2];
        const int q  = job & 3;
        const int token0 = bt * BM;
        const int qbase  = q * QCODES;

        const size_t abase_g = (size_t)token0 * D_;
        const size_t qbase_g = (size_t)qbase * D_;

        // per-row top-2 for each of 2 warp_n groups (threads 0..127, row = tid)
        float rv[2][2]; int ri[2][2];
        #pragma unroll
        for (int gg = 0; gg < 2; gg++) {
            rv[gg][0] = -CUDART_INF_F; rv[gg][1] = -CUDART_INF_F;
            ri[gg][0] = 0; ri[gg][1] = 0;
        }

        auto issue = [&](int s) {
            uint32_t sb = dbase + (uint32_t)(s % NSTAGE) * ST_B;
            const size_t koff = (size_t)((s & 7) * KS);
            const size_t bg = qbase_g + (size_t)((s >> 3) * BN) * D_ + koff;
            #pragma unroll
            for (int rep = 0; rep < 4; rep++) {
                size_t ar = abase_g + ld_rowD[rep] + koff;
                uint32_t o = sb + ld_off[rep];
                cp_async16(o,          g_xh + ar);
                cp_async16(o + TILE16, g_eh + bg + ld_rowD[rep]);
            }
            cp_commit();
        };

        issue(0);
        issue(1);

        uint32_t acc[2][8][2];   // fp16x2 accumulators

        #pragma unroll 1
        for (int s = 0; s < NSLJ; s++) {
            const int c = s >> 3, ks = s & 7;
            if (s + 2 < NSLJ) cp_wait1(); else cp_wait0();
            __syncthreads();
            if (s + 2 < NSLJ) issue(s + 2);   // 3 stages: refill (s+2)%3, safe

            if (ks == 0) {
                if (tid < BN) se2[tid] = g_e2h[qbase + c * BN + tid];
                #pragma unroll
                for (int mt = 0; mt < 2; mt++)
                    #pragma unroll
                    for (int nt = 0; nt < 8; nt++) {
                        acc[mt][nt][0] = 0u; acc[mt][nt][1] = 0u;
                    }
            }

            const uint32_t sb = dbase + (uint32_t)(s % NSTAGE) * ST_B;
            const uint32_t aH = sb;
            const uint32_t bH = sb + TILE16;

            #pragma unroll
            for (int kk = 0; kk < 4; kk++) {
                uint32_t ah[2][4];
                #pragma unroll
                for (int mt = 0; mt < 2; mt++) {
                    uint32_t off = abase[mt] + (uint32_t)((((kk * 2) + achunk_l) ^ rmod) << 4);
                    ldsm4(ah[mt], aH + off);
                }
                #pragma unroll
                for (int np = 0; np < 4; np++) {
                    uint32_t off = bbase[np] + (uint32_t)((((kk * 2) + bchunk_l) ^ rmod) << 4);
                    uint32_t bh[4];
                    ldsm4(bh, bH + off);
                    #pragma unroll
                    for (int half = 0; half < 2; half++) {
                        const int nt = 2 * np + half;
                        #pragma unroll
                        for (int mt = 0; mt < 2; mt++)
                            mma_f16acc(acc[mt][nt], ah[mt], bh + 2 * half);
                    }
                }
            }

            if (ks == 7) {
                // per-chunk argmax epilogue
                float tv1[4], tv2[4];
                int   ti1[4], ti2[4];
                #pragma unroll
                for (int sl = 0; sl < 4; sl++) {
                    tv1[sl] = -CUDART_INF_F; tv2[sl] = -CUDART_INF_F;
                    ti1[sl] = 0; ti2[sl] = 0;
                }
                #pragma unroll
                for (int nt = 0; nt < 8; nt++) {
                    int colb = warp_n * 64 + nt * 8 + tig * 2;
                    float e0 = se2[colb], e1 = se2[colb + 1];
                    int code0 = qbase + c * BN + colb;
                    #pragma unroll
                    for (int mt = 0; mt < 2; mt++) {
                        float2 f0 = __half22float2(*reinterpret_cast<const __half2*>(&acc[mt][nt][0]));
                        float2 f1 = __half22float2(*reinterpret_cast<const __half2*>(&acc[mt][nt][1]));
                        upd2(tv1[2*mt], ti1[2*mt], tv2[2*mt], ti2[2*mt], f0.x - e0, code0);
                        upd2(tv1[2*mt], ti1[2*mt], tv2[2*mt], ti2[2*mt], f0.y - e1, code0 + 1);
                        upd2(tv1[2*mt+1], ti1[2*mt+1], tv2[2*mt+1], ti2[2*mt+1], f1.x - e0, code0);
                        upd2(tv1[2*mt+1], ti1[2*mt+1], tv2[2*mt+1], ti2[2*mt+1], f1.y - e1, code0 + 1);
                    }
                }
                #pragma unroll
                for (int off = 1; off < 4; off <<= 1) {
                    #pragma unroll
                    for (int sl = 0; sl < 4; sl++) {
                        float w1 = __shfl_xor_sync(0xffffffffu, tv1[sl], off);
                        int   j1 = __shfl_xor_sync(0xffffffffu, ti1[sl], off);
                        float w2 = __shfl_xor_sync(0xffffffffu, tv2[sl], off);
                        int   j2 = __shfl_xor_sync(0xffffffffu, ti2[sl], off);
                        merge2(tv1[sl], ti1[sl], tv2[sl], ti2[sl], w1, j1, w2, j2);
                    }
                }
                if (tig == 0) {
                    #pragma unroll
                    for (int sl = 0; sl < 4; sl++) {
                        int row = warp_m * 32 + (sl >> 1) * 16 + g + ((sl & 1) << 3);
                        red[warp_n][row] = make_float4(tv1[sl], __int_as_float(ti1[sl]),
                                                       tv2[sl], __int_as_float(ti2[sl]));
                    }
                }
                __syncthreads();
                if (tid < BM) {
                    #pragma unroll
                    for (int wn = 0; wn < 2; wn++) {
                        float4 r0 = red[wn][tid];
                        merge2(rv[wn][0], ri[wn][0], rv[wn][1], ri[wn][1],
                               r0.x, __float_as_int(r0.y), r0.z, __float_as_int(r0.w));
                    }
                }
                // next slab's leading __syncthreads orders red reuse
            }
        }

        // ---- exact fp32 rescore of 4 candidates; write per-quarter result ----
        __syncthreads();
        if (tid < BM) {
            int row = tid;
            int token = token0 + row;
            const float* xr = x + (size_t)token * D_;
            float bv = -CUDART_INF_F; int bi = 0x7fffffff;
            #pragma unroll
            for (int gg = 0; gg < 2; gg++) {
                #pragma unroll
                for (int k = 0; k < 2; k++) {
                    int cidx = ri[gg][k];
                    const float* ep = embed + (size_t)cidx * D_;
                    float sdot = 0.f;
                    #pragma unroll 4
                    for (int d = 0; d < D_; d += 4) {
                        float4 xv = *reinterpret_cast<const float4*>(xr + d);
                        float4 ev = *reinterpret_cast<const float4*>(ep + d);
                        sdot = fmaf(xv.x, ev.x, sdot); sdot = fmaf(xv.y, ev.y, sdot);
                        sdot = fmaf(xv.z, ev.z, sdot); sdot = fmaf(xv.w, ev.w, sdot);
                    }
                    sdot -= __ldg(&g_e2h[cidx]);
                    if (better(sdot, cidx, bv, bi)) { bv = sdot; bi = cidx; }
                }
            }
            g_part[(token << 2) | q] = make_float2(bv, __int_as_float(bi));
        }
    }
}

// ---------------- combine: cross-quarter argmax + gather + mask ----------------
__global__ void combine_kernel(const int* __restrict__ input_length,
                               const float* __restrict__ embed,
                               float* __restrict__ out)
{
    __shared__ int sIdx[128];
    const int bt = blockIdx.x;
    const int token0 = bt * 128;
    const int batch = token0 >> 11;
    const int len = input_length[batch];
    int active = len - (token0 & 2047);
    active = active < 0 ? 0 : (active > 128 ? 128 : active);
    const int tid = threadIdx.x;

    float* outi = out + (size_t)NTOK * D_;

    if (tid < 128) {
        int token = token0 + tid;
        float bv = -CUDART_INF_F; int bi = 0x7fffffff;
        if (tid < active) {
            #pragma unroll
            for (int q = 0; q < 4; q++) {
                float2 p = g_part[(token << 2) | q];
                int ii = __float_as_int(p.y);
                if (better(p.x, ii, bv, bi)) { bv = p.x; bi = ii; }
            }
        }
        sIdx[tid] = bi;
        outi[token] = (tid < active) ? (float)bi : -1.0f;
    }
    __syncthreads();

    float4* qo = reinterpret_cast<float4*>(out + (size_t)token0 * D_);
    const float4 z = make_float4(0.f, 0.f, 0.f, 0.f);
    for (int v = tid; v < 128 * (D_ / 4); v += 256) {
        int r  = v >> 7;
        int dc = v & 127;
        float4 val = z;
        if (r < active)
            val = reinterpret_cast<const float4*>(embed + (size_t)sIdx[r] * D_)[dc];
        qo[v] = val;
    }
}

// ---------------------------------------------------------------------------
extern "C" void kernel_launch(void* const* d_in, const int* in_sizes, int n_in,
                              void* d_out, int out_size)
{
    const float* x     = (const float*)d_in[0];
    const int*   ilen  = (const int*)  d_in[1];
    const float* embed = (const float*)d_in[2];
    float* out = (float*)d_out;

    cudaFuncSetAttribute(vq_mma_kernel,
                         cudaFuncAttributeMaxDynamicSharedMemorySize, DYN_SMEM);

    conv_x_kernel<<<(NTOK * D_ / 8 + 255) / 256, 256>>>(x, NTOK * D_ / 8);
    conv_e_kernel<<<C_ / 8, 256>>>(embed);
    build_kernel<<<1, 256>>>(ilen);
    vq_mma_kernel<<<GRID, NTHREADS, DYN_SMEM>>>(x, ilen, embed, out);
    combine_kernel<<<NTOK / 128, 256>>>(ilen, embed, out);
}

// round 15
// speedup vs baseline: 1.2393x; 1.0200x over previous
#include <cuda_runtime.h>
#include <cuda_fp16.h>
#include <math_constants.h>
#include <cstdint>

// ---------------- problem constants ----------------
#define B_   16
#define S_   2048
#define D_   512
#define C_   8192
#define NTOK (B_*S_)

// ---------------- tiling (R12 geometry, fp16 acc, pipelined frags) ----------------
#define BM 128
#define BN 128
#define KS 64                     // K per slab
#define NKS (D_/KS)               // 8
#define QCODES (C_/4)             // 2048 codes per quarter job
#define QCH (QCODES/BN)           // 16 chunks per job
#define NSLJ (QCH*NKS)            // 128 slabs per job
#define TILE16 16384              // 128 rows x 128B fp16 tile
#define ST_B (2*TILE16)           // A, B = 32KB per stage
#define NSTAGE 3
#define DYN_SMEM (NSTAGE*ST_B)    // 96KB
#define NTHREADS 256
#define NTILES (NTOK/BM)          // 256 token tiles
#define GRID 296                  // 2 CTAs per SM

// ---------------- device scratch ----------------
__device__ __half g_xh[NTOK*D_];
__device__ __half g_eh[C_*D_];
__device__ float  g_e2h[C_];
__device__ float2 g_part[NTOK*4];   // per (token, quarter): {val, idx-bits}
__device__ int    g_active[NTILES];
__device__ int    g_nactive;
__device__ int    g_counter;

// ---------------- helpers ----------------
__device__ __forceinline__ uint32_t smem_u32(const void* p) {
    uint32_t a;
    asm("{ .reg .u64 t; cvta.to.shared.u64 t, %1; cvt.u32.u64 %0, t; }" : "=r"(a) : "l"(p));
    return a;
}
__device__ __forceinline__ void cp_async16(uint32_t saddr, const void* gptr) {
    asm volatile("cp.async.cg.shared.global [%0], [%1], 16;\n" :: "r"(saddr), "l"(gptr));
}
__device__ __forceinline__ void cp_commit() { asm volatile("cp.async.commit_group;\n"); }
__device__ __forceinline__ void cp_wait1()  { asm volatile("cp.async.wait_group 1;\n" ::: "memory"); }
__device__ __forceinline__ void cp_wait0()  { asm volatile("cp.async.wait_group 0;\n" ::: "memory"); }

__device__ __forceinline__ void ldsm4(uint32_t* r, uint32_t addr) {
    asm volatile("ldmatrix.sync.aligned.m8n8.x4.shared.b16 {%0,%1,%2,%3}, [%4];"
                 : "=r"(r[0]), "=r"(r[1]), "=r"(r[2]), "=r"(r[3]) : "r"(addr));
}
// fp16-accumulator MMA
__device__ __forceinline__ void mma_f16acc(uint32_t* d, const uint32_t* a, const uint32_t* b) {
    asm("mma.sync.aligned.m16n8k16.row.col.f16.f16.f16.f16 "
        "{%0,%1}, {%2,%3,%4,%5}, {%6,%7}, {%0,%1};"
        : "+r"(d[0]), "+r"(d[1])
        : "r"(a[0]), "r"(a[1]), "r"(a[2]), "r"(a[3]), "r"(b[0]), "r"(b[1]));
}

__device__ __forceinline__ bool better(float a, int ia, float b, int ib) {
    return (a > b) || (a == b && ia < ib);
}
__device__ __forceinline__ void upd2(float& v1, int& i1, float& v2, int& i2, float s, int c) {
    if (better(s, c, v1, i1)) { v2 = v1; i2 = i1; v1 = s; i1 = c; }
    else if (better(s, c, v2, i2)) { v2 = s; i2 = c; }
}
__device__ __forceinline__ void merge2(float& v1, int& i1, float& v2, int& i2,
                                       float w1, int j1, float w2, int j2) {
    if (better(w1, j1, v1, i1)) {
        if (better(v1, i1, w2, j2)) { v2 = v1; i2 = i1; } else { v2 = w2; i2 = j2; }
        v1 = w1; i1 = j1;
    } else if (better(w1, j1, v2, i2)) { v2 = w1; i2 = j1; }
}

// ---------------- prep kernels ----------------
__global__ void conv_x_kernel(const float* __restrict__ src, int n8) {
    int i = blockIdx.x * blockDim.x + threadIdx.x;
    if (i >= n8) return;
    const float4* s4 = reinterpret_cast<const float4*>(src);
    float4 v0 = s4[2 * i], v1 = s4[2 * i + 1];
    float vv[8] = {v0.x, v0.y, v0.z, v0.w, v1.x, v1.y, v1.z, v1.w};
    __align__(16) __half h[8];
    #pragma unroll
    for (int k = 0; k < 8; k++) h[k] = __float2half(vv[k]);
    reinterpret_cast<uint4*>(g_xh)[i] = *reinterpret_cast<uint4*>(h);
}

__global__ void conv_e_kernel(const float* __restrict__ embed) {
    int warp = threadIdx.x >> 5, lane = threadIdx.x & 31;
    int c = blockIdx.x * 8 + warp;
    if (c >= C_) return;
    const float* row = embed + (size_t)c * D_;
    float s = 0.f;
    #pragma unroll
    for (int i = lane; i < D_ / 8; i += 32) {
        const float4* s4 = reinterpret_cast<const float4*>(row) + 2 * i;
        float4 v0 = s4[0], v1 = s4[1];
        float vv[8] = {v0.x, v0.y, v0.z, v0.w, v1.x, v1.y, v1.z, v1.w};
        __align__(16) __half h[8];
        #pragma unroll
        for (int k = 0; k < 8; k++) {
            h[k] = __float2half(vv[k]);
            s = fmaf(vv[k], vv[k], s);
        }
        reinterpret_cast<uint4*>(g_eh + (size_t)c * D_)[i] = *reinterpret_cast<uint4*>(h);
    }
    #pragma unroll
    for (int o = 16; o > 0; o >>= 1) s += __shfl_xor_sync(0xffffffffu, s, o);
    if (lane == 0) g_e2h[c] = 0.5f * s;
}

__global__ void build_kernel(const int* __restrict__ input_length) {
    __shared__ int cnt;
    int t = threadIdx.x;
    if (t == 0) { cnt = 0; g_counter = 0; }
    __syncthreads();
    if (t < NTILES) {
        int batch = t >> 4, tile = t & 15;
        if (input_length[batch] > tile * BM) {
            int p = atomicAdd(&cnt, 1); g_active[p] = t;
        }
    }
    __syncthreads();
    if (t == 0) g_nactive = cnt;
}

// ---------------- main MMA kernel (2 CTAs/SM) ----------------
__global__ void __launch_bounds__(NTHREADS, 2)
vq_mma_kernel(const float* __restrict__ x,
              const int*   __restrict__ input_length,
              const float* __restrict__ embed,
              float*       __restrict__ out)
{
    extern __shared__ char dsm[];
    __shared__ float4 red[2][BM];
    __shared__ float  se2[BN];
    __shared__ int    s_job;

    const int tid    = threadIdx.x;
    const int wid    = tid >> 5;
    const int lane   = tid & 31;
    const int warp_m = wid & 3;     // 0..3 : 32 rows each
    const int warp_n = wid >> 2;    // 0..1 : 64 cols each
    const int g      = lane >> 2;
    const int tig    = lane & 3;

    const uint32_t dbase = smem_u32(dsm);

    // loader geometry: 4 reps x 2 tiles
    uint32_t ld_off[4]; int ld_rowD[4];
    #pragma unroll
    for (int rep = 0; rep < 4; rep++) {
        int idx = tid + rep * NTHREADS;
        int row = idx >> 3, ch = idx & 7;
        ld_off[rep]  = (uint32_t)(row * 128) + (uint32_t)((ch ^ (row & 7)) << 4);
        ld_rowD[rep] = row * D_ + ch * 8;
    }

    // per-lane ldmatrix geometry
    const int arow_l   = (lane & 7) + (((lane >> 3) & 1) << 3);
    const int achunk_l = (lane >> 4);
    const int brow_l   = (lane & 7) + (((lane >> 4) & 1) << 3);
    const int bchunk_l = (lane >> 3) & 1;
    const int rmod     = lane & 7;

    uint32_t abase[2];
    #pragma unroll
    for (int mt = 0; mt < 2; mt++)
        abase[mt] = (uint32_t)((warp_m * 32 + mt * 16 + arow_l) * 128);
    uint32_t bbase[4];
    #pragma unroll
    for (int np = 0; np < 4; np++)
        bbase[np] = (uint32_t)((warp_n * 64 + np * 16 + brow_l) * 128);

    while (true) {
        __syncthreads();
        if (tid == 0) s_job = atomicAdd(&g_counter, 1);
        __syncthreads();
        int job = s_job;
        if (job >= 4 * g_nactive) break;
        const int bt = g_active[job >> 2];
        const int q  = job & 3;
        const int token0 = bt * BM;
        const int qbase  = q * QCODES;

        const size_t abase_g = (size_t)token0 * D_;
        const size_t qbase_g = (size_t)qbase * D_;

        // per-row top-2 for each of 2 warp_n groups (threads 0..127, row = tid)
        float rv[2][2]; int ri[2][2];
        #pragma unroll
        for (int gg = 0; gg < 2; gg++) {
            rv[gg][0] = -CUDART_INF_F; rv[gg][1] = -CUDART_INF_F;
            ri[gg][0] = 0; ri[gg][1] = 0;
        }

        auto issue = [&](int s) {
            uint32_t sb = dbase + (uint32_t)(s % NSTAGE) * ST_B;
            const size_t koff = (size_t)((s & 7) * KS);
            const size_t bg = qbase_g + (size_t)((s >> 3) * BN) * D_ + koff;
            #pragma unroll
            for (int rep = 0; rep < 4; rep++) {
                size_t ar = abase_g + ld_rowD[rep] + koff;
                uint32_t o = sb + ld_off[rep];
                cp_async16(o,          g_xh + ar);
                cp_async16(o + TILE16, g_eh + bg + ld_rowD[rep]);
            }
            cp_commit();
        };

        issue(0);
        issue(1);

        uint32_t acc[2][8][2];   // fp16x2 accumulators

        #pragma unroll 1
        for (int s = 0; s < NSLJ; s++) {
            const int c = s >> 3, ks = s & 7;
            if (s + 2 < NSLJ) cp_wait1(); else cp_wait0();
            __syncthreads();
            if (s + 2 < NSLJ) issue(s + 2);   // 3 stages: refill (s+2)%3, safe

            if (ks == 0) {
                if (tid < BN) se2[tid] = g_e2h[qbase + c * BN + tid];
                #pragma unroll
                for (int mt = 0; mt < 2; mt++)
                    #pragma unroll
                    for (int nt = 0; nt < 8; nt++) {
                        acc[mt][nt][0] = 0u; acc[mt][nt][1] = 0u;
                    }
            }

            const uint32_t sb = dbase + (uint32_t)(s % NSTAGE) * ST_B;
            const uint32_t aH = sb;
            const uint32_t bH = sb + TILE16;

            // ---- software-pipelined fragment loads: double buffer over kk ----
            uint32_t ah[2][2][4];   // [buf][mt][4]
            uint32_t bh[2][4][4];   // [buf][np][4]
            #pragma unroll
            for (int mt = 0; mt < 2; mt++)
                ldsm4(ah[0][mt], aH + abase[mt] + (uint32_t)((achunk_l ^ rmod) << 4));
            #pragma unroll
            for (int np = 0; np < 4; np++)
                ldsm4(bh[0][np], bH + bbase[np] + (uint32_t)((bchunk_l ^ rmod) << 4));

            #pragma unroll
            for (int kk = 0; kk < 4; kk++) {
                const int cur = kk & 1, nxt = cur ^ 1;
                if (kk < 3) {
                    const int k2 = (kk + 1) * 2;
                    #pragma unroll
                    for (int mt = 0; mt < 2; mt++)
                        ldsm4(ah[nxt][mt], aH + abase[mt] +
                              (uint32_t)(((k2 + achunk_l) ^ rmod) << 4));
                    #pragma unroll
                    for (int np = 0; np < 4; np++)
                        ldsm4(bh[nxt][np], bH + bbase[np] +
                              (uint32_t)(((k2 + bchunk_l) ^ rmod) << 4));
                }
                #pragma unroll
                for (int np = 0; np < 4; np++)
                    #pragma unroll
                    for (int half = 0; half < 2; half++) {
                        const int nt = 2 * np + half;
                        #pragma unroll
                        for (int mt = 0; mt < 2; mt++)
                            mma_f16acc(acc[mt][nt], ah[cur][mt], bh[cur][np] + 2 * half);
                    }
            }

            if (ks == 7) {
                // per-chunk argmax epilogue
                float tv1[4], tv2[4];
                int   ti1[4], ti2[4];
                #pragma unroll
                for (int sl = 0; sl < 4; sl++) {
                    tv1[sl] = -CUDART_INF_F; tv2[sl] = -CUDART_INF_F;
                    ti1[sl] = 0; ti2[sl] = 0;
                }
                #pragma unroll
                for (int nt = 0; nt < 8; nt++) {
                    int colb = warp_n * 64 + nt * 8 + tig * 2;
                    float e0 = se2[colb], e1 = se2[colb + 1];
                    int code0 = qbase + c * BN + colb;
                    #pragma unroll
                    for (int mt = 0; mt < 2; mt++) {
                        float2 f0 = __half22float2(*reinterpret_cast<const __half2*>(&acc[mt][nt][0]));
                        float2 f1 = __half22float2(*reinterpret_cast<const __half2*>(&acc[mt][nt][1]));
                        upd2(tv1[2*mt], ti1[2*mt], tv2[2*mt], ti2[2*mt], f0.x - e0, code0);
                        upd2(tv1[2*mt], ti1[2*mt], tv2[2*mt], ti2[2*mt], f0.y - e1, code0 + 1);
                        upd2(tv1[2*mt+1], ti1[2*mt+1], tv2[2*mt+1], ti2[2*mt+1], f1.x - e0, code0);
                        upd2(tv1[2*mt+1], ti1[2*mt+1], tv2[2*mt+1], ti2[2*mt+1], f1.y - e1, code0 + 1);
                    }
                }
                #pragma unroll
                for (int off = 1; off < 4; off <<= 1) {
                    #pragma unroll
                    for (int sl = 0; sl < 4; sl++) {
                        float w1 = __shfl_xor_sync(0xffffffffu, tv1[sl], off);
                        int   j1 = __shfl_xor_sync(0xffffffffu, ti1[sl], off);
                        float w2 = __shfl_xor_sync(0xffffffffu, tv2[sl], off);
                        int   j2 = __shfl_xor_sync(0xffffffffu, ti2[sl], off);
                        merge2(tv1[sl], ti1[sl], tv2[sl], ti2[sl], w1, j1, w2, j2);
                    }
                }
                if (tig == 0) {
                    #pragma unroll
                    for (int sl = 0; sl < 4; sl++) {
                        int row = warp_m * 32 + (sl >> 1) * 16 + g + ((sl & 1) << 3);
                        red[warp_n][row] = make_float4(tv1[sl], __int_as_float(ti1[sl]),
                                                       tv2[sl], __int_as_float(ti2[sl]));
                    }
                }
                __syncthreads();
                if (tid < BM) {
                    #pragma unroll
                    for (int wn = 0; wn < 2; wn++) {
                        float4 r0 = red[wn][tid];
                        merge2(rv[wn][0], ri[wn][0], rv[wn][1], ri[wn][1],
                               r0.x, __float_as_int(r0.y), r0.z, __float_as_int(r0.w));
                    }
                }
                // next slab's leading __syncthreads orders red reuse
            }
        }

        // ---- exact fp32 rescore of 4 candidates; write per-quarter result ----
        __syncthreads();
        if (tid < BM) {
            int row = tid;
            int token = token0 + row;
            const float* xr = x + (size_t)token * D_;
            float bv = -CUDART_INF_F; int bi = 0x7fffffff;
            #pragma unroll
            for (int gg = 0; gg < 2; gg++) {
                #pragma unroll
                for (int k = 0; k < 2; k++) {
                    int cidx = ri[gg][k];
                    const float* ep = embed + (size_t)cidx * D_;
                    float sdot = 0.f;
                    #pragma unroll 4
                    for (int d = 0; d < D_; d += 4) {
                        float4 xv = *reinterpret_cast<const float4*>(xr + d);
                        float4 ev = *reinterpret_cast<const float4*>(ep + d);
                        sdot = fmaf(xv.x, ev.x, sdot); sdot = fmaf(xv.y, ev.y, sdot);
                        sdot = fmaf(xv.z, ev.z, sdot); sdot = fmaf(xv.w, ev.w, sdot);
                    }
                    sdot -= __ldg(&g_e2h[cidx]);
                    if (better(sdot, cidx, bv, bi)) { bv = sdot; bi = cidx; }
                }
            }
            g_part[(token << 2) | q] = make_float2(bv, __int_as_float(bi));
        }
    }
}

// ---------------- combine: cross-quarter argmax + gather + mask ----------------
__global__ void combine_kernel(const int* __restrict__ input_length,
                               const float* __restrict__ embed,
                               float* __restrict__ out)
{
    __shared__ int sIdx[128];
    const int bt = blockIdx.x;
    const int token0 = bt * 128;
    const int batch = token0 >> 11;
    const int len = input_length[batch];
    int active = len - (token0 & 2047);
    active = active < 0 ? 0 : (active > 128 ? 128 : active);
    const int tid = threadIdx.x;

    float* outi = out + (size_t)NTOK * D_;

    if (tid < 128) {
        int token = token0 + tid;
        float bv = -CUDART_INF_F; int bi = 0x7fffffff;
        if (tid < active) {
            #pragma unroll
            for (int q = 0; q < 4; q++) {
                float2 p = g_part[(token << 2) | q];
                int ii = __float_as_int(p.y);
                if (better(p.x, ii, bv, bi)) { bv = p.x; bi = ii; }
            }
        }
        sIdx[tid] = bi;
        outi[token] = (tid < active) ? (float)bi : -1.0f;
    }
    __syncthreads();

    float4* qo = reinterpret_cast<float4*>(out + (size_t)token0 * D_);
    const float4 z = make_float4(0.f, 0.f, 0.f, 0.f);
    for (int v = tid; v < 128 * (D_ / 4); v += 256) {
        int r  = v >> 7;
        int dc = v & 127;
        float4 val = z;
        if (r < active)
            val = reinterpret_cast<const float4*>(embed + (size_t)sIdx[r] * D_)[dc];
        qo[v] = val;
    }
}

// ---------------------------------------------------------------------------
extern "C" void kernel_launch(void* const* d_in, const int* in_sizes, int n_in,
                              void* d_out, int out_size)
{
    const float* x     = (const float*)d_in[0];
    const int*   ilen  = (const int*)  d_in[1];
    const float* embed = (const float*)d_in[2];
    float* out = (float*)d_out;

    cudaFuncSetAttribute(vq_mma_kernel,
                         cudaFuncAttributeMaxDynamicSharedMemorySize, DYN_SMEM);

    conv_x_kernel<<<(NTOK * D_ / 8 + 255) / 256, 256>>>(x, NTOK * D_ / 8);
    conv_e_kernel<<<C_ / 8, 256>>>(embed);
    build_kernel<<<1, 256>>>(ilen);
    vq_mma_kernel<<<GRID, NTHREADS, DYN_SMEM>>>(x, ilen, embed, out);
    combine_kernel<<<NTOK / 128, 256>>>(ilen, embed, out);
}